// round 1
// baseline (speedup 1.0000x reference)
#include <cuda_runtime.h>
#include <cuda_bf16.h>
#include <math.h>

// ---------------------------------------------------------------------------
// Problem constants
// ---------------------------------------------------------------------------
#define BATCH    8
#define SEQ      1024
#define DMODEL   768
#define NHEADS   12
#define DHEAD    64
#define DMLP     3072
#define TOKENS   (BATCH * SEQ)        // 8192
#define DQKV     (3 * DMODEL)         // 2304
#define LN_EPS   1e-5f

// ---------------------------------------------------------------------------
// Device scratch (allocation-free rule: __device__ globals)
// ---------------------------------------------------------------------------
__device__ float g_x1[TOKENS * DMODEL];          // LN1 output
__device__ float g_qkv[TOKENS * DQKV];           // Q|K|V packed per token
__device__ float g_scores[(size_t)BATCH * NHEADS * SEQ * SEQ]; // 402 MB
__device__ float g_z[TOKENS * DMODEL];           // attention output (h,e) layout
__device__ float g_mid[TOKENS * DMODEL];         // resid_mid
__device__ float g_x2[TOKENS * DMODEL];          // LN2 output
__device__ float g_h[TOKENS * DMLP];             // MLP hidden
__device__ float g_wqkv[DMODEL * DQKV];          // packed QKV weight [d][j]
__device__ float g_bqkv[DQKV];                   // packed QKV bias

// ---------------------------------------------------------------------------
// Helpers
// ---------------------------------------------------------------------------
__device__ __forceinline__ float gelu_new_f(float x) {
    const float c = 0.7978845608028654f;  // sqrt(2/pi)
    float x3 = x * x * x;
    float t = tanhf(c * (x + 0.044715f * x3));
    return 0.5f * x * (1.0f + t);
}

// ---------------------------------------------------------------------------
// Pack QKV weights: Wp[d][j], j = which*768 + h*64 + e  <-  W_X[h][d][e]
// ---------------------------------------------------------------------------
__global__ void pack_wqkv_kernel(const float* __restrict__ WQ,
                                 const float* __restrict__ WK,
                                 const float* __restrict__ WV,
                                 const float* __restrict__ bQ,
                                 const float* __restrict__ bK,
                                 const float* __restrict__ bV) {
    int idx = blockIdx.x * 256 + threadIdx.x;
    if (idx < DMODEL * DQKV) {
        int d = idx / DQKV;
        int j = idx - d * DQKV;
        int which = j / DMODEL;
        int he = j - which * DMODEL;
        int h = he >> 6;
        int e = he & 63;
        const float* W = (which == 0) ? WQ : (which == 1) ? WK : WV;
        g_wqkv[idx] = W[h * (DMODEL * DHEAD) + d * DHEAD + e];
    }
    if (idx < DQKV) {
        int which = idx / DMODEL;
        int he = idx - which * DMODEL;
        const float* bb = (which == 0) ? bQ : (which == 1) ? bK : bV;
        g_bqkv[idx] = bb[he];
    }
}

// ---------------------------------------------------------------------------
// LayerNorm: one block per row (768 wide, 256 threads -> 3 elems/thread)
// ---------------------------------------------------------------------------
__global__ void ln_kernel(const float* __restrict__ x,
                          const float* __restrict__ w,
                          const float* __restrict__ b,
                          float* __restrict__ y) {
    int row = blockIdx.x;
    const float* xr = x + (size_t)row * DMODEL;
    float* yr = y + (size_t)row * DMODEL;
    int tid = threadIdx.x;
    __shared__ float shm[8];

    float v0 = xr[tid], v1 = xr[tid + 256], v2 = xr[tid + 512];
    float s = v0 + v1 + v2;
    #pragma unroll
    for (int o = 16; o > 0; o >>= 1) s += __shfl_xor_sync(0xffffffffu, s, o);
    if ((tid & 31) == 0) shm[tid >> 5] = s;
    __syncthreads();
    s = 0.f;
    #pragma unroll
    for (int i = 0; i < 8; i++) s += shm[i];
    float mean = s * (1.0f / DMODEL);
    __syncthreads();

    float d0 = v0 - mean, d1 = v1 - mean, d2 = v2 - mean;
    float vs = d0 * d0 + d1 * d1 + d2 * d2;
    #pragma unroll
    for (int o = 16; o > 0; o >>= 1) vs += __shfl_xor_sync(0xffffffffu, vs, o);
    if ((tid & 31) == 0) shm[tid >> 5] = vs;
    __syncthreads();
    vs = 0.f;
    #pragma unroll
    for (int i = 0; i < 8; i++) vs += shm[i];
    float inv = rsqrtf(vs * (1.0f / DMODEL) + LN_EPS);

    yr[tid]       = d0 * inv * w[tid]       + b[tid];
    yr[tid + 256] = d1 * inv * w[tid + 256] + b[tid + 256];
    yr[tid + 512] = d2 * inv * w[tid + 512] + b[tid + 512];
}

// ---------------------------------------------------------------------------
// Tiled SGEMM: C[M,N] = A[M,K] @ B[K,N] + bias[N]  (+ optional GELU / residual)
// BM=BN=128, BK=8, 256 threads, 8x8 per thread. M,N,K all multiples assumed.
// ---------------------------------------------------------------------------
template<int ACT_GELU, int RES>
__global__ void __launch_bounds__(256)
sgemm_kernel(const float* __restrict__ A, const float* __restrict__ B,
             const float* __restrict__ bias, const float* __restrict__ R,
             float* __restrict__ C, int M, int N, int K) {
    __shared__ float As[8][128];
    __shared__ float Bs[8][128];

    int bx = blockIdx.x;  // N tile
    int by = blockIdx.y;  // M tile
    int tid = threadIdx.x;
    int tx = tid & 15;
    int ty = tid >> 4;

    const float* Aptr = A + (size_t)(by * 128) * K;
    const float* Bptr = B + bx * 128;

    float acc[8][8];
    #pragma unroll
    for (int i = 0; i < 8; i++)
        #pragma unroll
        for (int j = 0; j < 8; j++) acc[i][j] = 0.f;

    int arow = tid >> 1, acol = (tid & 1) * 4;
    int brow = tid >> 5, bcol = (tid & 31) * 4;

    for (int k0 = 0; k0 < K; k0 += 8) {
        float4 av = *(const float4*)(Aptr + (size_t)arow * K + k0 + acol);
        float4 bv = *(const float4*)(Bptr + (size_t)(k0 + brow) * N + bcol);
        As[acol + 0][arow] = av.x;
        As[acol + 1][arow] = av.y;
        As[acol + 2][arow] = av.z;
        As[acol + 3][arow] = av.w;
        *(float4*)(&Bs[brow][bcol]) = bv;
        __syncthreads();

        #pragma unroll
        for (int kk = 0; kk < 8; kk++) {
            float a[8], bb[8];
            *(float4*)(a)     = *(const float4*)(&As[kk][ty * 8]);
            *(float4*)(a + 4) = *(const float4*)(&As[kk][ty * 8 + 4]);
            *(float4*)(bb)     = *(const float4*)(&Bs[kk][tx * 8]);
            *(float4*)(bb + 4) = *(const float4*)(&Bs[kk][tx * 8 + 4]);
            #pragma unroll
            for (int i = 0; i < 8; i++)
                #pragma unroll
                for (int j = 0; j < 8; j++)
                    acc[i][j] += a[i] * bb[j];
        }
        __syncthreads();
    }

    int row0 = by * 128 + ty * 8;
    int col0 = bx * 128 + tx * 8;
    #pragma unroll
    for (int i = 0; i < 8; i++) {
        int row = row0 + i;
        #pragma unroll
        for (int j4 = 0; j4 < 8; j4 += 4) {
            float4 v;
            v.x = acc[i][j4 + 0] + bias[col0 + j4 + 0];
            v.y = acc[i][j4 + 1] + bias[col0 + j4 + 1];
            v.z = acc[i][j4 + 2] + bias[col0 + j4 + 2];
            v.w = acc[i][j4 + 3] + bias[col0 + j4 + 3];
            if (ACT_GELU) {
                v.x = gelu_new_f(v.x); v.y = gelu_new_f(v.y);
                v.z = gelu_new_f(v.z); v.w = gelu_new_f(v.w);
            }
            if (RES) {
                float4 r = *(const float4*)(R + (size_t)row * N + col0 + j4);
                v.x += r.x; v.y += r.y; v.z += r.z; v.w += r.w;
            }
            *(float4*)(C + (size_t)row * N + col0 + j4) = v;
        }
    }
}

// ---------------------------------------------------------------------------
// Attention scores: S[b,h,q,k] = (Q_bh @ K_bh^T) / 8, lower triangle only.
// grid: (kt=16, qt=16, bh=96), 256 threads, 64x64 tile, 4x4 per thread.
// ---------------------------------------------------------------------------
__global__ void __launch_bounds__(256)
scores_kernel(const float* __restrict__ qkv, float* __restrict__ S) {
    int kt = blockIdx.x, qt = blockIdx.y, bh = blockIdx.z;
    if (kt > qt) return;
    int b = bh / NHEADS, h = bh - b * NHEADS;

    __shared__ float Qs[64][65];
    __shared__ float Ks[64][65];

    int tid = threadIdx.x;
    int lr = tid >> 2, lc = (tid & 3) * 16;

    const float* qbase = qkv + (size_t)(b * SEQ + qt * 64) * DQKV + h * DHEAD;
    const float* kbase = qkv + (size_t)(b * SEQ + kt * 64) * DQKV + DMODEL + h * DHEAD;

    #pragma unroll
    for (int c = 0; c < 16; c += 4) {
        float4 v = *(const float4*)(qbase + (size_t)lr * DQKV + lc + c);
        Qs[lr][lc + c + 0] = v.x; Qs[lr][lc + c + 1] = v.y;
        Qs[lr][lc + c + 2] = v.z; Qs[lr][lc + c + 3] = v.w;
        float4 w = *(const float4*)(kbase + (size_t)lr * DQKV + lc + c);
        Ks[lr][lc + c + 0] = w.x; Ks[lr][lc + c + 1] = w.y;
        Ks[lr][lc + c + 2] = w.z; Ks[lr][lc + c + 3] = w.w;
    }
    __syncthreads();

    int tx = tid & 15, ty = tid >> 4;
    float acc[4][4];
    #pragma unroll
    for (int i = 0; i < 4; i++)
        #pragma unroll
        for (int j = 0; j < 4; j++) acc[i][j] = 0.f;

    #pragma unroll 8
    for (int e = 0; e < 64; e++) {
        float a[4], bb[4];
        #pragma unroll
        for (int i = 0; i < 4; i++) a[i] = Qs[ty * 4 + i][e];
        #pragma unroll
        for (int j = 0; j < 4; j++) bb[j] = Ks[tx * 4 + j][e];
        #pragma unroll
        for (int i = 0; i < 4; i++)
            #pragma unroll
            for (int j = 0; j < 4; j++)
                acc[i][j] += a[i] * bb[j];
    }

    const float scale = 0.125f;  // 1/sqrt(64)
    float* sbase = S + ((size_t)bh * SEQ + qt * 64) * SEQ + kt * 64;
    #pragma unroll
    for (int i = 0; i < 4; i++) {
        int qg = qt * 64 + ty * 4 + i;
        #pragma unroll
        for (int j = 0; j < 4; j++) {
            int kg = kt * 64 + tx * 4 + j;
            if (kg <= qg)
                sbase[(size_t)(ty * 4 + i) * SEQ + tx * 4 + j] = acc[i][j] * scale;
        }
    }
}

// ---------------------------------------------------------------------------
// Causal softmax over k in [0, q]; zero-fills the diagonal-tile tail so the
// PV GEMM can read whole 64-wide tiles.  grid: (q=1024, bh=96), 128 threads.
// ---------------------------------------------------------------------------
__global__ void softmax_kernel(float* __restrict__ S) {
    int q = blockIdx.x, bh = blockIdx.y;
    float* row = S + ((size_t)bh * SEQ + q) * SEQ;
    int len = q + 1;
    int tid = threadIdx.x;
    __shared__ float shm[4];

    float m = -1e30f;
    for (int k = tid; k < len; k += 128) m = fmaxf(m, row[k]);
    #pragma unroll
    for (int o = 16; o > 0; o >>= 1) m = fmaxf(m, __shfl_xor_sync(0xffffffffu, m, o));
    if ((tid & 31) == 0) shm[tid >> 5] = m;
    __syncthreads();
    m = fmaxf(fmaxf(shm[0], shm[1]), fmaxf(shm[2], shm[3]));
    __syncthreads();

    float s = 0.f;
    for (int k = tid; k < len; k += 128) {
        float e = __expf(row[k] - m);
        row[k] = e;
        s += e;
    }
    #pragma unroll
    for (int o = 16; o > 0; o >>= 1) s += __shfl_xor_sync(0xffffffffu, s, o);
    if ((tid & 31) == 0) shm[tid >> 5] = s;
    __syncthreads();
    s = shm[0] + shm[1] + shm[2] + shm[3];
    float inv = 1.0f / s;
    for (int k = tid; k < len; k += 128) row[k] *= inv;

    int kend = ((q >> 6) + 1) << 6;
    for (int k = len + tid; k < kend; k += 128) row[k] = 0.f;
}

// ---------------------------------------------------------------------------
// PV: Z[b, q, (h,e)] = P_bh @ V_bh.  grid: (qt=16, bh=96), 256 threads.
// ---------------------------------------------------------------------------
__global__ void __launch_bounds__(256)
pv_kernel(const float* __restrict__ S, const float* __restrict__ qkv,
          float* __restrict__ Z) {
    int qt = blockIdx.x, bh = blockIdx.y;
    int b = bh / NHEADS, h = bh - b * NHEADS;

    __shared__ float Ps[64][65];
    __shared__ float Vs[64][65];

    int tid = threadIdx.x;
    int lr = tid >> 2, lc = (tid & 3) * 16;
    int tx = tid & 15, ty = tid >> 4;

    const float* srow = S + ((size_t)bh * SEQ + qt * 64) * SEQ;
    const float* vbase = qkv + (size_t)(b * SEQ) * DQKV + 2 * DMODEL + h * DHEAD;

    float acc[4][4];
    #pragma unroll
    for (int i = 0; i < 4; i++)
        #pragma unroll
        for (int j = 0; j < 4; j++) acc[i][j] = 0.f;

    for (int kt = 0; kt <= qt; kt++) {
        __syncthreads();
        #pragma unroll
        for (int c = 0; c < 16; c += 4) {
            float4 p = *(const float4*)(srow + (size_t)lr * SEQ + kt * 64 + lc + c);
            Ps[lr][lc + c + 0] = p.x; Ps[lr][lc + c + 1] = p.y;
            Ps[lr][lc + c + 2] = p.z; Ps[lr][lc + c + 3] = p.w;
            float4 v = *(const float4*)(vbase + (size_t)(kt * 64 + lr) * DQKV + lc + c);
            Vs[lr][lc + c + 0] = v.x; Vs[lr][lc + c + 1] = v.y;
            Vs[lr][lc + c + 2] = v.z; Vs[lr][lc + c + 3] = v.w;
        }
        __syncthreads();

        #pragma unroll 8
        for (int kk = 0; kk < 64; kk++) {
            float a[4], bb[4];
            #pragma unroll
            for (int i = 0; i < 4; i++) a[i] = Ps[ty * 4 + i][kk];
            #pragma unroll
            for (int j = 0; j < 4; j++) bb[j] = Vs[kk][tx * 4 + j];
            #pragma unroll
            for (int i = 0; i < 4; i++)
                #pragma unroll
                for (int j = 0; j < 4; j++)
                    acc[i][j] += a[i] * bb[j];
        }
    }

    #pragma unroll
    for (int i = 0; i < 4; i++) {
        int t = b * SEQ + qt * 64 + ty * 4 + i;
        #pragma unroll
        for (int j = 0; j < 4; j++) {
            Z[(size_t)t * DMODEL + h * DHEAD + tx * 4 + j] = acc[i][j];
        }
    }
}

// ---------------------------------------------------------------------------
// Host launcher
// ---------------------------------------------------------------------------
extern "C" void kernel_launch(void* const* d_in, const int* in_sizes, int n_in,
                              void* d_out, int out_size) {
    const float* resid_pre = (const float*)d_in[0];
    const float* W_Q  = (const float*)d_in[1];
    const float* W_K  = (const float*)d_in[2];
    const float* W_V  = (const float*)d_in[3];
    const float* W_O  = (const float*)d_in[4];
    const float* b_Q  = (const float*)d_in[5];
    const float* b_K  = (const float*)d_in[6];
    const float* b_V  = (const float*)d_in[7];
    const float* b_O  = (const float*)d_in[8];
    const float* ln1_w = (const float*)d_in[9];
    const float* ln1_b = (const float*)d_in[10];
    const float* ln2_w = (const float*)d_in[11];
    const float* ln2_b = (const float*)d_in[12];
    const float* W_in  = (const float*)d_in[13];
    const float* b_in  = (const float*)d_in[14];
    const float* W_out = (const float*)d_in[15];
    const float* b_out = (const float*)d_in[16];
    float* out = (float*)d_out;

    float *p_x1, *p_qkv, *p_scores, *p_z, *p_mid, *p_x2, *p_h, *p_wqkv, *p_bqkv;
    cudaGetSymbolAddress((void**)&p_x1, g_x1);
    cudaGetSymbolAddress((void**)&p_qkv, g_qkv);
    cudaGetSymbolAddress((void**)&p_scores, g_scores);
    cudaGetSymbolAddress((void**)&p_z, g_z);
    cudaGetSymbolAddress((void**)&p_mid, g_mid);
    cudaGetSymbolAddress((void**)&p_x2, g_x2);
    cudaGetSymbolAddress((void**)&p_h, g_h);
    cudaGetSymbolAddress((void**)&p_wqkv, g_wqkv);
    cudaGetSymbolAddress((void**)&p_bqkv, g_bqkv);

    // 1. pack QKV weights+biases
    pack_wqkv_kernel<<<(DMODEL * DQKV + 255) / 256, 256>>>(W_Q, W_K, W_V, b_Q, b_K, b_V);

    // 2. LN1
    ln_kernel<<<TOKENS, 256>>>(resid_pre, ln1_w, ln1_b, p_x1);

    // 3. QKV GEMM: [8192x768] @ [768x2304]
    sgemm_kernel<0, 0><<<dim3(DQKV / 128, TOKENS / 128), 256>>>(
        p_x1, p_wqkv, p_bqkv, nullptr, p_qkv, TOKENS, DQKV, DMODEL);

    // 4. scores (causal lower-tri tiles only)
    scores_kernel<<<dim3(SEQ / 64, SEQ / 64, BATCH * NHEADS), 256>>>(p_qkv, p_scores);

    // 5. causal softmax
    softmax_kernel<<<dim3(SEQ, BATCH * NHEADS), 128>>>(p_scores);

    // 6. PV
    pv_kernel<<<dim3(SEQ / 64, BATCH * NHEADS), 256>>>(p_scores, p_qkv, p_z);

    // 7. O-projection + residual: resid_mid = resid_pre + Z @ W_O + b_O
    //    W_O [h,e,d] is contiguous as [(h*64+e) x 768] row-major.
    sgemm_kernel<0, 1><<<dim3(DMODEL / 128, TOKENS / 128), 256>>>(
        p_z, W_O, b_O, resid_pre, p_mid, TOKENS, DMODEL, DMODEL);

    // 8. LN2
    ln_kernel<<<TOKENS, 256>>>(p_mid, ln2_w, ln2_b, p_x2);

    // 9. MLP in + GELU: [8192x768] @ [768x3072]
    sgemm_kernel<1, 0><<<dim3(DMLP / 128, TOKENS / 128), 256>>>(
        p_x2, W_in, b_in, nullptr, p_h, TOKENS, DMLP, DMODEL);

    // 10. MLP out + residual: out = resid_mid + H @ W_out + b_out
    sgemm_kernel<0, 1><<<dim3(DMODEL / 128, TOKENS / 128), 256>>>(
        p_h, W_out, b_out, p_mid, out, TOKENS, DMODEL, DMLP);
}

// round 3
// speedup vs baseline: 2.3440x; 2.3440x over previous
#include <cuda_runtime.h>
#include <cuda_bf16.h>
#include <math.h>
#include <stdint.h>

// ---------------------------------------------------------------------------
// Problem constants
// ---------------------------------------------------------------------------
#define BATCH    8
#define SEQ      1024
#define DMODEL   768
#define NHEADS   12
#define DHEAD    64
#define DMLP     3072
#define TOKENS   (BATCH * SEQ)        // 8192
#define DQKV     (3 * DMODEL)         // 2304
#define LN_EPS   1e-5f

// ---------------------------------------------------------------------------
// Device scratch (allocation-free rule: __device__ globals)
// ---------------------------------------------------------------------------
__device__ float g_x1[TOKENS * DMODEL];          // LN1 output (tf32-rounded)
__device__ float g_qkv[TOKENS * DQKV];           // Q|K|V packed per token
__device__ float g_scores[(size_t)BATCH * NHEADS * SEQ * SEQ]; // 402 MB
__device__ float g_z[TOKENS * DMODEL];           // attention out (h,e), tf32-rounded
__device__ float g_mid[TOKENS * DMODEL];         // resid_mid (fp32)
__device__ float g_x2[TOKENS * DMODEL];          // LN2 output (tf32-rounded)
__device__ float g_h[TOKENS * DMLP];             // MLP hidden (tf32-rounded)
__device__ float g_wqkv[DQKV * DMODEL];          // [j=2304 rows][k=768] K-major
__device__ float g_bqkv[DQKV];
__device__ float g_wot[DMODEL * DMODEL];         // W_O^T  [d=768][he=768]
__device__ float g_wint[DMLP * DMODEL];          // W_in^T [m=3072][d=768]
__device__ float g_woutt[DMODEL * DMLP];         // W_out^T[d=768][m=3072]

// ---------------------------------------------------------------------------
// Helpers (sm_80-baseline PTX only — no arch-conditional instructions)
// ---------------------------------------------------------------------------
__device__ __forceinline__ uint32_t smem_u32(const void* p) {
    uint32_t a;
    asm("{ .reg .u64 t; cvta.to.shared.u64 t, %1; cvt.u32.u64 %0, t; }" : "=r"(a) : "l"(p));
    return a;
}
__device__ __forceinline__ float tf32r(float x) {
    uint32_t u;
    asm("cvt.rn.tf32.f32 %0, %1;" : "=r"(u) : "f"(x));
    return __uint_as_float(u);
}
#define CP_ASYNC16(dst, src) \
    asm volatile("cp.async.cg.shared.global [%0], [%1], 16;" :: "r"(dst), "l"(src) : "memory")
#define CP_COMMIT() asm volatile("cp.async.commit_group;" ::: "memory")

// m16n8k8 tf32 MMA (fp32 accumulate). A row-major, B col-major fragments.
__device__ __forceinline__ void mma_tf32(float* d, const uint32_t* a,
                                         const uint32_t* b, const float* c) {
    asm volatile("mma.sync.aligned.m16n8k8.row.col.f32.tf32.tf32.f32 "
        "{%0,%1,%2,%3}, {%4,%5,%6,%7}, {%8,%9}, {%10,%11,%12,%13};"
        : "=f"(d[0]), "=f"(d[1]), "=f"(d[2]), "=f"(d[3])
        : "r"(a[0]), "r"(a[1]), "r"(a[2]), "r"(a[3]),
          "r"(b[0]), "r"(b[1]),
          "f"(c[0]), "f"(c[1]), "f"(c[2]), "f"(c[3]));
}

__device__ __forceinline__ float gelu_new_f(float x) {
    const float c = 0.7978845608028654f;
    float t = tanhf(c * (x + 0.044715f * x * x * x));
    return 0.5f * x * (1.0f + t);
}

// ---------------------------------------------------------------------------
// Weight prep: transposed + tf32-rounded copies
// ---------------------------------------------------------------------------
__global__ void transpose_cvt(const float* __restrict__ in, float* __restrict__ out,
                              int Kd, int Nd) {   // in[Kd][Nd] -> out[Nd][Kd]
    __shared__ float t[32][33];
    int k0 = blockIdx.y * 32, n0 = blockIdx.x * 32;
    int tx = threadIdx.x, ty = threadIdx.y;
    #pragma unroll
    for (int i = 0; i < 32; i += 8)
        t[ty + i][tx] = in[(size_t)(k0 + ty + i) * Nd + n0 + tx];
    __syncthreads();
    #pragma unroll
    for (int i = 0; i < 32; i += 8)
        out[(size_t)(n0 + ty + i) * Kd + k0 + tx] = tf32r(t[tx][ty + i]);
}

// W_{Q,K,V}[h][d][e] -> g_wqkv[(which*768 + h*64 + e)][d], tf32-rounded
__global__ void pack_wqkv_t(const float* __restrict__ WQ, const float* __restrict__ WK,
                            const float* __restrict__ WV) {
    __shared__ float t[32][33];
    int z = blockIdx.z; int which = z / NHEADS, h = z % NHEADS;
    const float* W = ((which == 0) ? WQ : (which == 1) ? WK : WV) + (size_t)h * DMODEL * DHEAD;
    int d0 = blockIdx.y * 32, e0 = blockIdx.x * 32;
    int tx = threadIdx.x, ty = threadIdx.y;
    #pragma unroll
    for (int i = 0; i < 32; i += 8)
        t[ty + i][tx] = W[(size_t)(d0 + ty + i) * DHEAD + e0 + tx];
    __syncthreads();
    float* out = g_wqkv + (size_t)(which * DMODEL + h * DHEAD) * DMODEL;
    #pragma unroll
    for (int i = 0; i < 32; i += 8)
        out[(size_t)(e0 + ty + i) * DMODEL + d0 + tx] = tf32r(t[tx][ty + i]);
}

__global__ void pack_bqkv(const float* __restrict__ bQ, const float* __restrict__ bK,
                          const float* __restrict__ bV) {
    int i = blockIdx.x * 256 + threadIdx.x;
    if (i < DQKV) {
        int w = i / DMODEL, he = i - w * DMODEL;
        g_bqkv[i] = ((w == 0) ? bQ : (w == 1) ? bK : bV)[he];
    }
}

// ---------------------------------------------------------------------------
// LayerNorm (tf32-rounded output; consumers are GEMMs)
// ---------------------------------------------------------------------------
__global__ void ln_kernel(const float* __restrict__ x, const float* __restrict__ w,
                          const float* __restrict__ b, float* __restrict__ y) {
    int row = blockIdx.x;
    const float* xr = x + (size_t)row * DMODEL;
    float* yr = y + (size_t)row * DMODEL;
    int tid = threadIdx.x;
    __shared__ float shm[8];

    float v0 = xr[tid], v1 = xr[tid + 256], v2 = xr[tid + 512];
    float s = v0 + v1 + v2;
    #pragma unroll
    for (int o = 16; o > 0; o >>= 1) s += __shfl_xor_sync(0xffffffffu, s, o);
    if ((tid & 31) == 0) shm[tid >> 5] = s;
    __syncthreads();
    s = 0.f;
    #pragma unroll
    for (int i = 0; i < 8; i++) s += shm[i];
    float mean = s * (1.0f / DMODEL);
    __syncthreads();

    float d0 = v0 - mean, d1 = v1 - mean, d2 = v2 - mean;
    float vs = d0 * d0 + d1 * d1 + d2 * d2;
    #pragma unroll
    for (int o = 16; o > 0; o >>= 1) vs += __shfl_xor_sync(0xffffffffu, vs, o);
    if ((tid & 31) == 0) shm[tid >> 5] = vs;
    __syncthreads();
    vs = 0.f;
    #pragma unroll
    for (int i = 0; i < 8; i++) vs += shm[i];
    float inv = rsqrtf(vs * (1.0f / DMODEL) + LN_EPS);

    yr[tid]       = tf32r(d0 * inv * w[tid]       + b[tid]);
    yr[tid + 256] = tf32r(d1 * inv * w[tid + 256] + b[tid + 256]);
    yr[tid + 512] = tf32r(d2 * inv * w[tid + 512] + b[tid + 512]);
}

// ---------------------------------------------------------------------------
// mma.sync tf32 GEMM: C[M,N] = A[M,K] @ Bt[N,K]^T + bias (+GELU/+cvt/+residual)
// 128x128 block tile, BK=32, 8 warps (4x2), warp tile 32x64, double-buffered
// cp.async. SMEM rows padded to 36 floats => conflict-free fragment loads.
// ---------------------------------------------------------------------------
#define BK 32
#define LDS_A 36
#define STAGE_F (128 * LDS_A)                 // floats per operand per stage
#define DSMEM_GEMM (4 * STAGE_F * 4)          // 2 operands * 2 stages, bytes

template<int GELU, int RES, int CVT>
__global__ void __launch_bounds__(256, 2)
mma_gemm(const float* __restrict__ A, const float* __restrict__ Bt,
         const float* __restrict__ bias, const float* __restrict__ R,
         float* __restrict__ C, int M, int N, int K) {
    extern __shared__ float sm[];
    float* As = sm;                    // [2][STAGE_F]
    float* Bs = sm + 2 * STAGE_F;      // [2][STAGE_F]
    const uint32_t sA32 = smem_u32(As);
    const uint32_t sB32 = smem_u32(Bs);

    const int tid = threadIdx.x;
    const int m0 = blockIdx.y * 128, n0 = blockIdx.x * 128;
    const int NC = K / BK;

    const int wid = tid >> 5, lane = tid & 31;
    const int wm = (wid & 3) * 32, wn = (wid >> 2) * 64;
    const int gr = lane >> 2, gc = lane & 3;

    float acc[2][8][4];
    #pragma unroll
    for (int mi = 0; mi < 2; mi++)
        #pragma unroll
        for (int ni = 0; ni < 8; ni++)
            #pragma unroll
            for (int q = 0; q < 4; q++) acc[mi][ni][q] = 0.f;

    // async-load one BK-chunk of A and B into stage st
    auto issue = [&](int c, int st) {
        const float* Ag = A + (size_t)m0 * K + c * BK;
        const float* Bg = Bt + (size_t)n0 * K + c * BK;
        uint32_t dA = sA32 + (uint32_t)st * STAGE_F * 4;
        uint32_t dB = sB32 + (uint32_t)st * STAGE_F * 4;
        #pragma unroll
        for (int i = 0; i < 4; i++) {
            int g = tid + 256 * i;               // 1024 16B-granules per operand
            int row = g >> 3, col = (g & 7) * 4;
            uint32_t off = (uint32_t)(row * LDS_A + col) * 4;
            CP_ASYNC16(dA + off, Ag + (size_t)row * K + col);
            CP_ASYNC16(dB + off, Bg + (size_t)row * K + col);
        }
        CP_COMMIT();
    };

    issue(0, 0);

    for (int c = 0; c < NC; c++) {
        const int st = c & 1;
        if (c + 1 < NC) {
            issue(c + 1, st ^ 1);
            asm volatile("cp.async.wait_group %0;" :: "n"(1) : "memory");
        } else {
            asm volatile("cp.async.wait_group %0;" :: "n"(0) : "memory");
        }
        __syncthreads();

        const float* Ab = As + st * STAGE_F;
        const float* Bb = Bs + st * STAGE_F;
        #pragma unroll
        for (int ks = 0; ks < BK / 8; ks++) {
            const int k0 = ks * 8;
            uint32_t af[2][4];
            #pragma unroll
            for (int mi = 0; mi < 2; mi++) {
                const float* p = Ab + (wm + mi * 16 + gr) * LDS_A + k0 + gc;
                af[mi][0] = __float_as_uint(p[0]);
                af[mi][1] = __float_as_uint(p[8 * LDS_A]);
                af[mi][2] = __float_as_uint(p[4]);
                af[mi][3] = __float_as_uint(p[8 * LDS_A + 4]);
            }
            #pragma unroll
            for (int ni = 0; ni < 8; ni++) {
                const float* q = Bb + (wn + ni * 8 + gr) * LDS_A + k0 + gc;
                uint32_t bf[2];
                bf[0] = __float_as_uint(q[0]);
                bf[1] = __float_as_uint(q[4]);
                #pragma unroll
                for (int mi = 0; mi < 2; mi++)
                    mma_tf32(acc[mi][ni], af[mi], bf, acc[mi][ni]);
            }
        }
        __syncthreads();
    }

    // epilogue: thread owns rows (wm + mi*16 + gr, +8), cols (wn + ni*8 + gc*2, +1)
    const int mrow = m0 + wm + gr;
    const int ncol = n0 + wn + gc * 2;
    #pragma unroll
    for (int mi = 0; mi < 2; mi++) {
        #pragma unroll
        for (int half = 0; half < 2; half++) {
            int row = mrow + mi * 16 + half * 8;
            float* Crow = C + (size_t)row * N;
            const float* Rrow = R + (size_t)row * N;
            #pragma unroll
            for (int ni = 0; ni < 8; ni++) {
                int col = ncol + ni * 8;
                float2 v;
                v.x = acc[mi][ni][half * 2 + 0] + bias[col];
                v.y = acc[mi][ni][half * 2 + 1] + bias[col + 1];
                if (GELU) { v.x = gelu_new_f(v.x); v.y = gelu_new_f(v.y); }
                if (CVT)  { v.x = tf32r(v.x);      v.y = tf32r(v.y); }
                if (RES)  { v.x += Rrow[col];      v.y += Rrow[col + 1]; }
                *(float2*)(Crow + col) = v;
            }
        }
    }
}

// ---------------------------------------------------------------------------
// Attention (fp32 SIMT; validated in R1)
// ---------------------------------------------------------------------------
__global__ void __launch_bounds__(256)
scores_kernel(const float* __restrict__ qkv, float* __restrict__ S) {
    int kt = blockIdx.x, qt = blockIdx.y, bh = blockIdx.z;
    if (kt > qt) return;
    int b = bh / NHEADS, h = bh - b * NHEADS;

    __shared__ float Qs[64][65];
    __shared__ float Ks[64][65];

    int tid = threadIdx.x;
    int lr = tid >> 2, lc = (tid & 3) * 16;

    const float* qbase = qkv + (size_t)(b * SEQ + qt * 64) * DQKV + h * DHEAD;
    const float* kbase = qkv + (size_t)(b * SEQ + kt * 64) * DQKV + DMODEL + h * DHEAD;

    #pragma unroll
    for (int c = 0; c < 16; c += 4) {
        float4 v = *(const float4*)(qbase + (size_t)lr * DQKV + lc + c);
        Qs[lr][lc + c + 0] = v.x; Qs[lr][lc + c + 1] = v.y;
        Qs[lr][lc + c + 2] = v.z; Qs[lr][lc + c + 3] = v.w;
        float4 w = *(const float4*)(kbase + (size_t)lr * DQKV + lc + c);
        Ks[lr][lc + c + 0] = w.x; Ks[lr][lc + c + 1] = w.y;
        Ks[lr][lc + c + 2] = w.z; Ks[lr][lc + c + 3] = w.w;
    }
    __syncthreads();

    int tx = tid & 15, ty = tid >> 4;
    float acc[4][4];
    #pragma unroll
    for (int i = 0; i < 4; i++)
        #pragma unroll
        for (int j = 0; j < 4; j++) acc[i][j] = 0.f;

    #pragma unroll 8
    for (int e = 0; e < 64; e++) {
        float a[4], bb[4];
        #pragma unroll
        for (int i = 0; i < 4; i++) a[i] = Qs[ty * 4 + i][e];
        #pragma unroll
        for (int j = 0; j < 4; j++) bb[j] = Ks[tx * 4 + j][e];
        #pragma unroll
        for (int i = 0; i < 4; i++)
            #pragma unroll
            for (int j = 0; j < 4; j++)
                acc[i][j] += a[i] * bb[j];
    }

    const float scale = 0.125f;
    float* sbase = S + ((size_t)bh * SEQ + qt * 64) * SEQ + kt * 64;
    #pragma unroll
    for (int i = 0; i < 4; i++) {
        int qg = qt * 64 + ty * 4 + i;
        #pragma unroll
        for (int j = 0; j < 4; j++) {
            int kg = kt * 64 + tx * 4 + j;
            if (kg <= qg)
                sbase[(size_t)(ty * 4 + i) * SEQ + tx * 4 + j] = acc[i][j] * scale;
        }
    }
}

__global__ void softmax_kernel(float* __restrict__ S) {
    int q = blockIdx.x, bh = blockIdx.y;
    float* row = S + ((size_t)bh * SEQ + q) * SEQ;
    int len = q + 1;
    int tid = threadIdx.x;
    __shared__ float shm[4];

    float m = -1e30f;
    for (int k = tid; k < len; k += 128) m = fmaxf(m, row[k]);
    #pragma unroll
    for (int o = 16; o > 0; o >>= 1) m = fmaxf(m, __shfl_xor_sync(0xffffffffu, m, o));
    if ((tid & 31) == 0) shm[tid >> 5] = m;
    __syncthreads();
    m = fmaxf(fmaxf(shm[0], shm[1]), fmaxf(shm[2], shm[3]));
    __syncthreads();

    float s = 0.f;
    for (int k = tid; k < len; k += 128) {
        float e = __expf(row[k] - m);
        row[k] = e;
        s += e;
    }
    #pragma unroll
    for (int o = 16; o > 0; o >>= 1) s += __shfl_xor_sync(0xffffffffu, s, o);
    if ((tid & 31) == 0) shm[tid >> 5] = s;
    __syncthreads();
    s = shm[0] + shm[1] + shm[2] + shm[3];
    float inv = 1.0f / s;
    for (int k = tid; k < len; k += 128) row[k] *= inv;

    int kend = ((q >> 6) + 1) << 6;
    for (int k = len + tid; k < kend; k += 128) row[k] = 0.f;
}

__global__ void __launch_bounds__(256)
pv_kernel(const float* __restrict__ S, const float* __restrict__ qkv,
          float* __restrict__ Z) {
    int qt = blockIdx.x, bh = blockIdx.y;
    int b = bh / NHEADS, h = bh - b * NHEADS;

    __shared__ float Ps[64][65];
    __shared__ float Vs[64][65];

    int tid = threadIdx.x;
    int lr = tid >> 2, lc = (tid & 3) * 16;
    int tx = tid & 15, ty = tid >> 4;

    const float* srow = S + ((size_t)bh * SEQ + qt * 64) * SEQ;
    const float* vbase = qkv + (size_t)(b * SEQ) * DQKV + 2 * DMODEL + h * DHEAD;

    float acc[4][4];
    #pragma unroll
    for (int i = 0; i < 4; i++)
        #pragma unroll
        for (int j = 0; j < 4; j++) acc[i][j] = 0.f;

    for (int kt = 0; kt <= qt; kt++) {
        __syncthreads();
        #pragma unroll
        for (int c = 0; c < 16; c += 4) {
            float4 p = *(const float4*)(srow + (size_t)lr * SEQ + kt * 64 + lc + c);
            Ps[lr][lc + c + 0] = p.x; Ps[lr][lc + c + 1] = p.y;
            Ps[lr][lc + c + 2] = p.z; Ps[lr][lc + c + 3] = p.w;
            float4 v = *(const float4*)(vbase + (size_t)(kt * 64 + lr) * DQKV + lc + c);
            Vs[lr][lc + c + 0] = v.x; Vs[lr][lc + c + 1] = v.y;
            Vs[lr][lc + c + 2] = v.z; Vs[lr][lc + c + 3] = v.w;
        }
        __syncthreads();

        #pragma unroll 8
        for (int kk = 0; kk < 64; kk++) {
            float a[4], bb[4];
            #pragma unroll
            for (int i = 0; i < 4; i++) a[i] = Ps[ty * 4 + i][kk];
            #pragma unroll
            for (int j = 0; j < 4; j++) bb[j] = Vs[kk][tx * 4 + j];
            #pragma unroll
            for (int i = 0; i < 4; i++)
                #pragma unroll
                for (int j = 0; j < 4; j++)
                    acc[i][j] += a[i] * bb[j];
        }
    }

    #pragma unroll
    for (int i = 0; i < 4; i++) {
        int t = b * SEQ + qt * 64 + ty * 4 + i;
        #pragma unroll
        for (int j = 0; j < 4; j++) {
            Z[(size_t)t * DMODEL + h * DHEAD + tx * 4 + j] = tf32r(acc[i][j]);
        }
    }
}

// ---------------------------------------------------------------------------
// Host launcher
// ---------------------------------------------------------------------------
extern "C" void kernel_launch(void* const* d_in, const int* in_sizes, int n_in,
                              void* d_out, int out_size) {
    const float* resid_pre = (const float*)d_in[0];
    const float* W_Q  = (const float*)d_in[1];
    const float* W_K  = (const float*)d_in[2];
    const float* W_V  = (const float*)d_in[3];
    const float* W_O  = (const float*)d_in[4];
    const float* b_Q  = (const float*)d_in[5];
    const float* b_K  = (const float*)d_in[6];
    const float* b_V  = (const float*)d_in[7];
    const float* b_O  = (const float*)d_in[8];
    const float* ln1_w = (const float*)d_in[9];
    const float* ln1_b = (const float*)d_in[10];
    const float* ln2_w = (const float*)d_in[11];
    const float* ln2_b = (const float*)d_in[12];
    const float* W_in  = (const float*)d_in[13];
    const float* b_in  = (const float*)d_in[14];
    const float* W_out = (const float*)d_in[15];
    const float* b_out = (const float*)d_in[16];
    float* out = (float*)d_out;

    float *p_x1, *p_qkv, *p_scores, *p_z, *p_mid, *p_x2, *p_h;
    float *p_wqkv, *p_bqkv, *p_wot, *p_wint, *p_woutt;
    cudaGetSymbolAddress((void**)&p_x1, g_x1);
    cudaGetSymbolAddress((void**)&p_qkv, g_qkv);
    cudaGetSymbolAddress((void**)&p_scores, g_scores);
    cudaGetSymbolAddress((void**)&p_z, g_z);
    cudaGetSymbolAddress((void**)&p_mid, g_mid);
    cudaGetSymbolAddress((void**)&p_x2, g_x2);
    cudaGetSymbolAddress((void**)&p_h, g_h);
    cudaGetSymbolAddress((void**)&p_wqkv, g_wqkv);
    cudaGetSymbolAddress((void**)&p_bqkv, g_bqkv);
    cudaGetSymbolAddress((void**)&p_wot, g_wot);
    cudaGetSymbolAddress((void**)&p_wint, g_wint);
    cudaGetSymbolAddress((void**)&p_woutt, g_woutt);

    cudaFuncSetAttribute(mma_gemm<0, 0, 0>, cudaFuncAttributeMaxDynamicSharedMemorySize, DSMEM_GEMM);
    cudaFuncSetAttribute(mma_gemm<0, 1, 0>, cudaFuncAttributeMaxDynamicSharedMemorySize, DSMEM_GEMM);
    cudaFuncSetAttribute(mma_gemm<1, 0, 1>, cudaFuncAttributeMaxDynamicSharedMemorySize, DSMEM_GEMM);

    // weight prep (transposed K-major + tf32 rounding)
    pack_wqkv_t<<<dim3(DHEAD / 32, DMODEL / 32, 3 * NHEADS), dim3(32, 8)>>>(W_Q, W_K, W_V);
    pack_bqkv<<<(DQKV + 255) / 256, 256>>>(b_Q, b_K, b_V);
    transpose_cvt<<<dim3(DMODEL / 32, DMODEL / 32), dim3(32, 8)>>>(W_O, p_wot, DMODEL, DMODEL);
    transpose_cvt<<<dim3(DMLP / 32, DMODEL / 32), dim3(32, 8)>>>(W_in, p_wint, DMODEL, DMLP);
    transpose_cvt<<<dim3(DMODEL / 32, DMLP / 32), dim3(32, 8)>>>(W_out, p_woutt, DMLP, DMODEL);

    // LN1 -> QKV GEMM
    ln_kernel<<<TOKENS, 256>>>(resid_pre, ln1_w, ln1_b, p_x1);
    mma_gemm<0, 0, 0><<<dim3(DQKV / 128, TOKENS / 128), 256, DSMEM_GEMM>>>(
        p_x1, p_wqkv, p_bqkv, nullptr, p_qkv, TOKENS, DQKV, DMODEL);

    // attention core (fp32 SIMT)
    scores_kernel<<<dim3(SEQ / 64, SEQ / 64, BATCH * NHEADS), 256>>>(p_qkv, p_scores);
    softmax_kernel<<<dim3(SEQ, BATCH * NHEADS), 128>>>(p_scores);
    pv_kernel<<<dim3(SEQ / 64, BATCH * NHEADS), 256>>>(p_scores, p_qkv, p_z);

    // O-projection + residual
    mma_gemm<0, 1, 0><<<dim3(DMODEL / 128, TOKENS / 128), 256, DSMEM_GEMM>>>(
        p_z, p_wot, b_O, resid_pre, p_mid, TOKENS, DMODEL, DMODEL);

    // LN2 -> MLP
    ln_kernel<<<TOKENS, 256>>>(p_mid, ln2_w, ln2_b, p_x2);
    mma_gemm<1, 0, 1><<<dim3(DMLP / 128, TOKENS / 128), 256, DSMEM_GEMM>>>(
        p_x2, p_wint, b_in, nullptr, p_h, TOKENS, DMLP, DMODEL);
    mma_gemm<0, 1, 0><<<dim3(DMODEL / 128, TOKENS / 128), 256, DSMEM_GEMM>>>(
        p_h, p_woutt, b_out, p_mid, out, TOKENS, DMODEL, DMLP);
}